// round 13
// baseline (speedup 1.0000x reference)
#include <cuda_runtime.h>
#include <cuda_bf16.h>
#include <cstdint>

// Banded stereo cost volume, 3 scales fused.
// cost[j,h,x] = sum_c L[c,h,x] * R[c,h,x-j], zero when x<j.
//
// Round-2 scalar core (TJ=16 x TX=4 register tile, conflict-free LDS.128,
// zero-band tile skip), restructured for 2 CTAs per SM:
//   - scale-0 rows split into x-halves -> smem 90KB/CTA, two CTAs co-resident
//   - 256 threads, __launch_bounds__(256,2) caps regs at 125 -> RF fits 2 CTAs
//   - one CTA's FFMA stream overlaps the other's gmem->smem staging + barrier
//   - work granule <= 1.57M lane-FMAs -> greedy tail imbalance ~4%
// CTA order heavy-first: scale0 right halves (no zero band), scale0 left
// halves, scale1 rows, scale2 rows.

#define THREADS 256

template <int C, int H, int W, int D, int XW>
__device__ __forceinline__ void cost_volume_chunk(const float* __restrict__ L,
                                                  const float* __restrict__ R,
                                                  float* __restrict__ out,
                                                  int h, int X0, float* smem)
{
    constexpr int RW = D + XW;          // staged R window width
    float* sL = smem;                   // [C][XW]
    float* sR = smem + C * XW;          // [C][RW]

    const int tid = threadIdx.x;

    // Left zero pad: logical R[X0-D .. X0); zero where global index < 0.
    // X0 is either 0 (pad = D) or >= D (pad = 0).
    const int pad_len   = (X0 >= D) ? 0 : (D - X0);
    const int seg_start = X0 - D + pad_len;   // first staged global R column
    const int seg_len   = RW - pad_len;

    for (int i = tid; i < C * pad_len; i += THREADS) {
        int c = i / pad_len;
        int k = i - c * pad_len;
        sR[c * RW + k] = 0.0f;
    }

    // Stage L [X0, X0+XW) and R [seg_start, seg_start+seg_len) per channel.
    constexpr int WV = XW / 4;
    const float4* Lg = reinterpret_cast<const float4*>(L + (size_t)h * W + X0);
    const float4* Rg = reinterpret_cast<const float4*>(R + (size_t)h * W + seg_start);
    constexpr int CH_STRIDE_V = H * W / 4;
    const int SEGV = seg_len / 4;       // seg_start multiple of 4 -> aligned

    for (int i = tid; i < C * WV; i += THREADS) {
        int c  = i / WV;
        int xv = i - c * WV;
        reinterpret_cast<float4*>(sL + c * XW)[xv] = Lg[(size_t)c * CH_STRIDE_V + xv];
    }
    for (int i = tid; i < C * SEGV; i += THREADS) {
        int c  = i / SEGV;
        int xv = i - c * SEGV;
        reinterpret_cast<float4*>(sR + c * RW + pad_len)[xv] =
            Rg[(size_t)c * CH_STRIDE_V + xv];
    }
    __syncthreads();

    // Tile grid: TJ=16 disparities x TX=4 columns per tile.
    constexpr int NXT = XW / 4;             // pow2
    constexpr int NT  = (D / 16) * NXT;     // scale0 chunk: 768 = 3*256 exact

    for (int t = tid; t < NT; t += THREADS) {
        int jt = t / NXT;                   // shift (NXT pow2)
        int xt = t - jt * NXT;
        int j0 = jt * 16;
        int x0 = xt * 4;                    // local x within chunk

        float* op = out + (size_t)j0 * H * W + (size_t)h * W + X0 + x0;

        // Tile fully inside the x<j zero band: write zeros, skip compute.
        if (X0 + x0 + 3 < j0) {
            float4 z = make_float4(0.f, 0.f, 0.f, 0.f);
#pragma unroll
            for (int jj = 0; jj < 16; jj++)
                *reinterpret_cast<float4*>(op + (size_t)jj * H * W) = z;
            continue;
        }

        float acc[16][4];
#pragma unroll
        for (int jj = 0; jj < 16; jj++)
#pragma unroll
            for (int xi = 0; xi < 4; xi++)
                acc[jj][xi] = 0.0f;

        // sR index of logical R[X0+x-j] is x + D - j (x local).
        // Window base x0 + D - j0 - 16 >= 0, multiple of 4 (16B aligned).
        const int rbase = x0 + D - j0 - 16;

#pragma unroll 8
        for (int c = 0; c < C; c++) {
            const float* sLc = sL + c * XW + x0;
            const float* sRc = sR + c * RW + rbase;

            float4 l4 = *reinterpret_cast<const float4*>(sLc);
            float lv[4] = {l4.x, l4.y, l4.z, l4.w};

            float rv[20];
#pragma unroll
            for (int q = 0; q < 5; q++) {
                float4 r4 = *reinterpret_cast<const float4*>(sRc + 4 * q);
                rv[4 * q + 0] = r4.x; rv[4 * q + 1] = r4.y;
                rv[4 * q + 2] = r4.z; rv[4 * q + 3] = r4.w;
            }

            // k = 16 + xi - jj in [1, 19]
#pragma unroll
            for (int jj = 0; jj < 16; jj++)
#pragma unroll
                for (int xi = 0; xi < 4; xi++)
                    acc[jj][xi] = fmaf(lv[xi], rv[16 + xi - jj], acc[jj][xi]);
        }

#pragma unroll
        for (int jj = 0; jj < 16; jj++) {
            float4 o = make_float4(acc[jj][0], acc[jj][1], acc[jj][2], acc[jj][3]);
            *reinterpret_cast<float4*>(op + (size_t)jj * H * W) = o;
        }
    }
}

// Output layout: cv0 (1,192,256,512) | cv1 (1,96,128,256) | cv2 (1,48,64,128)
static constexpr size_t OUT0_ELEMS = (size_t)192 * 256 * 512;
static constexpr size_t OUT1_ELEMS = (size_t)96 * 128 * 256;

__global__ void __launch_bounds__(THREADS, 2)
cost_volume_fused_kernel(const float* __restrict__ L0, const float* __restrict__ R0,
                         const float* __restrict__ L1, const float* __restrict__ R1,
                         const float* __restrict__ L2, const float* __restrict__ R2,
                         float* __restrict__ out)
{
    extern __shared__ float smem[];
    const int b = blockIdx.x;

    if (b < 256) {
        // scale 0, RIGHT half (x in [256,512), no zero band) — heaviest first
        cost_volume_chunk<32, 256, 512, 192, 256>(L0, R0, out, b, 256, smem);
    } else if (b < 512) {
        // scale 0, LEFT half (x in [0,256))
        cost_volume_chunk<32, 256, 512, 192, 256>(L0, R0, out, b - 256, 0, smem);
    } else if (b < 640) {
        cost_volume_chunk<32, 128, 256, 96, 256>(L1, R1, out + OUT0_ELEMS,
                                                 b - 512, 0, smem);
    } else {
        cost_volume_chunk<32, 64, 128, 48, 128>(L2, R2,
                                                out + OUT0_ELEMS + OUT1_ELEMS,
                                                b - 640, 0, smem);
    }
}

extern "C" void kernel_launch(void* const* d_in, const int* in_sizes, int n_in,
                              void* d_out, int out_size)
{
    const float* L0 = (const float*)d_in[0];
    const float* R0 = (const float*)d_in[1];
    const float* L1 = (const float*)d_in[2];
    const float* R1 = (const float*)d_in[3];
    const float* L2 = (const float*)d_in[4];
    const float* R2 = (const float*)d_in[5];
    float* out = (float*)d_out;

    // Max smem per CTA: scale0 half-row = 32*(256 + 192+256)*4 = 90112 bytes
    // -> two CTAs co-resident (180224 < 228KB carveout).
    constexpr int SMEM_BYTES = 32 * (256 + 192 + 256) * 4;
    static bool attr_set = false;
    if (!attr_set) {
        cudaFuncSetAttribute(cost_volume_fused_kernel,
                             cudaFuncAttributeMaxDynamicSharedMemorySize, SMEM_BYTES);
        attr_set = true;
    }

    // 256 right halves + 256 left halves + 128 scale1 + 64 scale2 = 704 CTAs
    cost_volume_fused_kernel<<<704, THREADS, SMEM_BYTES>>>(L0, R0, L1, R1,
                                                           L2, R2, out);
}